// round 4
// baseline (speedup 1.0000x reference)
#include <cuda_runtime.h>
#include <math.h>

#define BB 16
#define CC 64
#define NN 4096
#define KK 128
#define MM 257
#define TEMBD 256
#define HH 128
#define MP 288
#define NSPLIT 16
#define PI_F 3.14159265358979323846f

// ---------------- device scratch ----------------
__device__ float g_tau[BB];
__device__ float g_gate[BB*MM];
__device__ float g_tvec[BB*CC];
__device__ int   g_midx[MP];
__device__ int   g_Mact;
__device__ float g_kcpt[MP];
__device__ float g_ccpt[MP];
__device__ float g_iwcpt[MP];
__device__ float g_Xr[(size_t)NSPLIT*BB*CC*MP];
__device__ float g_Xi[(size_t)NSPLIT*BB*CC*MP];
__device__ float g_Yr[(size_t)BB*CC*MP];
__device__ float g_Yi[(size_t)BB*CC*MP];

__device__ __forceinline__ float sigmoidf_(float x){ return 1.f/(1.f+expf(-x)); }
__device__ __forceinline__ float softplusf_(float x){ return log1pf(expf(x)); }

// ---------------- kernel A: per-batch MLP tau + tproj vec (16 blocks) ----------------
__global__ void __launch_bounds__(256) k_batch(const float* __restrict__ temb,
                                               const float* __restrict__ tproj_w,
                                               const float* __restrict__ tproj_b,
                                               const float* __restrict__ mlp_w1,
                                               const float* __restrict__ mlp_b1,
                                               const float* __restrict__ mlp_w2,
                                               const float* __restrict__ mlp_b2,
                                               const float* __restrict__ tau0p,
                                               const float* __restrict__ tau1p)
{
    int b = blockIdx.x;
    int tid = threadIdx.x;
    __shared__ float te[TEMBD], si[TEMBD];
    __shared__ float hid[HH];
    float v = temb[b*TEMBD + tid];
    te[tid] = v;
    si[tid] = v * sigmoidf_(v);
    __syncthreads();
    if (tid < HH) {
        float acc = mlp_b1[tid];
        const float* w = mlp_w1 + tid*TEMBD;
        #pragma unroll 8
        for (int t = 0; t < TEMBD; t++) acc = fmaf(te[t], w[t], acc);
        hid[tid] = acc * sigmoidf_(acc);
    } else if (tid < HH + CC) {
        int c = tid - HH;
        float acc = tproj_b[c];
        const float* w = tproj_w + c*TEMBD;
        #pragma unroll 8
        for (int t = 0; t < TEMBD; t++) acc = fmaf(si[t], w[t], acc);
        g_tvec[b*CC + c] = acc;
    }
    __syncthreads();
    if (tid == 0) {
        float acc = mlp_b2[0];
        for (int h = 0; h < HH; h++) acc = fmaf(hid[h], mlp_w2[h], acc);
        g_tau[b] = tau0p[0] + softplusf_(tau1p[0]) * tanhf(acc);
    }
}

// ---------------- kernel B: kappa, gates, compaction (1 block) ----------------
__global__ void __launch_bounds__(256) k_kappa(const float* __restrict__ kappa_raw,
                                               const float* __restrict__ gabor_c,
                                               const float* __restrict__ gabor_omega_raw,
                                               const float* __restrict__ alphap,
                                               const float* __restrict__ glowp,
                                               const float* __restrict__ gmidp,
                                               const float* __restrict__ ghighp)
{
    __shared__ float kpos[KK];
    __shared__ float kap[MM];
    __shared__ float gmax[MM];
    __shared__ float tau[BB];
    __shared__ float th1s, th2s;
    int tid = threadIdx.x;

    if (tid < KK) kpos[tid] = softplusf_(kappa_raw[tid]);
    if (tid < BB) tau[tid] = g_tau[tid];
    __syncthreads();
    if (tid == 0) {
        float s = 0.f;
        for (int k = 0; k < KK; k++) { s += kpos[k]; kpos[k] = s; }
        // sorted |kappa| = [0, kpos0,kpos0, kpos1,kpos1, ...], 257 values
        th1s = kpos[50]  + 0.4f*(kpos[51] - kpos[50]);
        th2s = kpos[101] + 0.8f*(kpos[102] - kpos[101]);
    }
    __syncthreads();

    float alpha = softplusf_(alphap[0]) + 1e-12f;
    float gl = sigmoidf_(glowp[0]);
    float gm = sigmoidf_(gmidp[0]);
    float gh = sigmoidf_(ghighp[0]);
    for (int m = tid; m < MM; m += blockDim.x) {
        float kv = (m < KK) ? -kpos[KK-1-m] : ((m == KK) ? 0.f : kpos[m-KK-1]);
        kap[m] = kv;
        float ka = fabsf(kv);
        float bandv = (ka <= th1s) ? gl : ((ka <= th2s) ? gm : gh);
        float mx = 0.f;
        for (int b = 0; b < BB; b++) {
            float g = bandv * sigmoidf_(alpha*(tau[b]-ka));
            g_gate[b*MM+m] = g;
            mx = fmaxf(mx, g);
        }
        gmax[m] = mx;
    }
    __syncthreads();

    if (tid == 0) {
        int cnt = 0;
        for (int m = 0; m < MM; m++) {
            if (gmax[m] > 1e-7f) {
                g_midx[cnt]  = m;
                g_kcpt[cnt]  = kap[m];
                g_ccpt[cnt]  = gabor_c[m];
                float om = fmaxf(softplusf_(gabor_omega_raw[m]), 1e-6f);
                g_iwcpt[cnt] = 1.f/om;
                cnt++;
            }
        }
        g_Mact = cnt;
        for (int j = cnt; j < MP; j++) { g_kcpt[j]=0.f; g_ccpt[j]=0.f; g_iwcpt[j]=1.f; g_midx[j]=0; }
    }
}

// ---------------- kernel 1: analysis (software-pipelined basis + GEMM) ----------------
// block: 32 modes x 256 n x 64 c, two n-halves merged in-block -> 16 partial slots
__global__ void __launch_bounds__(256) k_analysis(const float* __restrict__ x_feat,
                                                  const float* __restrict__ z)
{
    int mt = blockIdx.x;
    int ns = blockIdx.y;
    int b  = blockIdx.z;
    int Mact = g_Mact;
    int m0 = mt * 32;
    if (m0 >= Mact) return;

    __shared__ float km[32], cm[32], iw[32];
    __shared__ float cwb[2][64][32];
    __shared__ float swb[2][64][32];
    __shared__ float xb[2][64][68];

    int tid = threadIdx.x;
    if (tid < 32) {
        km[tid] = g_kcpt[m0+tid];
        cm[tid] = g_ccpt[m0+tid];
        iw[tid] = g_iwcpt[m0+tid];
    }

    int half = tid >> 7;
    int mg = tid & 7;
    int cg = (tid >> 3) & 15;
    int c_tid = tid & 63, q_tid = tid >> 6;
    float tvc = g_tvec[b*CC + c_tid];
    const float* zb = z + b*NN;
    int nbase0 = ns*256;

    float ar[4][4], ai[4][4];
    #pragma unroll
    for (int a = 0; a < 4; a++)
        #pragma unroll
        for (int k = 0; k < 4; k++) { ar[a][k] = 0.f; ai[a][k] = 0.f; }

    __syncthreads();   // km/cm/iw visible before first basis gen

#define A_LOADX(t, bf) { \
    int n0_ = nbase0 + (t)*64; \
    const float4* xg_ = (const float4*)(x_feat + ((size_t)(b*CC + c_tid))*NN + n0_); \
    _Pragma("unroll") \
    for (int q_ = 0; q_ < 4; q_++) { \
        float4 v_ = xg_[q_tid*4 + q_]; \
        int nn_ = q_tid*16 + q_*4; \
        xb[bf][nn_+0][c_tid]=v_.x+tvc; xb[bf][nn_+1][c_tid]=v_.y+tvc; \
        xb[bf][nn_+2][c_tid]=v_.z+tvc; xb[bf][nn_+3][c_tid]=v_.w+tvc; } }

#define A_GENB(t, bf) { \
    int n0_ = nbase0 + (t)*64; \
    _Pragma("unroll") \
    for (int e_ = 0; e_ < 8; e_++) { \
        int idx_ = e_*256 + tid; \
        int nn_ = idx_ >> 5, mm_ = idx_ & 31; \
        float zv_ = __ldg(zb + n0_ + nn_); \
        float s_, c_; __sincosf(zv_*km[mm_], &s_, &c_); \
        float d_ = (zv_*(1.f/PI_F) - cm[mm_])*iw[mm_]; \
        float w_ = __expf(-0.5f*d_*d_); \
        cwb[bf][nn_][mm_] = c_*w_; swb[bf][nn_][mm_] = s_*w_; } }

    A_LOADX(0, 0);
    A_GENB(0, 0);
    __syncthreads();

    #pragma unroll
    for (int t = 0; t < 4; t++) {
        int cur = t & 1;
        if (t < 3) {
            int nxt = cur ^ 1;
            A_LOADX(t+1, nxt);
            A_GENB(t+1, nxt);
        }
        int nbase = half*32;
        #pragma unroll 4
        for (int n2 = 0; n2 < 32; n2++) {
            int nn = nbase + n2;
            float4 xv = *(const float4*)&xb[cur][nn][cg*4];
            float4 cv = *(const float4*)&cwb[cur][nn][mg*4];
            float4 sv = *(const float4*)&swb[cur][nn][mg*4];
            float xa[4] = {xv.x, xv.y, xv.z, xv.w};
            float ca[4] = {cv.x, cv.y, cv.z, cv.w};
            float sa[4] = {sv.x, sv.y, sv.z, sv.w};
            #pragma unroll
            for (int a = 0; a < 4; a++)
                #pragma unroll
                for (int k = 0; k < 4; k++) {
                    ar[a][k] = fmaf(xa[a], ca[k], ar[a][k]);
                    ai[a][k] = fmaf(xa[a], sa[k], ai[a][k]);
                }
        }
        __syncthreads();
    }

    // merge the two halves in-block (stage half 1 in smem, reuse basis buffers)
    float* stage = &cwb[0][0][0];   // 2*64*32 = 4096 floats available
    if (half == 1) {
        float* p = stage + (tid-128)*32;
        #pragma unroll
        for (int a = 0; a < 4; a++)
            #pragma unroll
            for (int k = 0; k < 4; k++) { p[a*8+k] = ar[a][k]; p[a*8+4+k] = ai[a][k]; }
    }
    __syncthreads();
    if (half == 0) {
        float* p = stage + tid*32;
        #pragma unroll
        for (int a = 0; a < 4; a++)
            #pragma unroll
            for (int k = 0; k < 4; k++) { ar[a][k] += p[a*8+k]; ai[a][k] += p[a*8+4+k]; }
        size_t base = ((size_t)(ns*BB + b)*CC + cg*4)*MP + m0 + mg*4;
        #pragma unroll
        for (int a = 0; a < 4; a++) {
            float4 r; r.x=ar[a][0]; r.y=ar[a][1]; r.z=ar[a][2]; r.w=ar[a][3];
            float4 i; i.x=ai[a][0]; i.y=ai[a][1]; i.z=ai[a][2]; i.w=ai[a][3];
            *(float4*)&g_Xr[base + (size_t)a*MP] = r;
            *(float4*)&g_Xi[base + (size_t)a*MP] = i;
        }
    }
#undef A_LOADX
#undef A_GENB
}

// ---------------- kernel 2: combine splits, gate, complex weight (zero-pads Y) ----------------
__global__ void k_comb(const float* __restrict__ wr, const float* __restrict__ wi)
{
    int bc = blockIdx.x;
    int b = bc / CC, c = bc % CC;
    int j = threadIdx.x;
    size_t o = ((size_t)b*CC + c)*MP + j;
    if (j >= g_Mact) { g_Yr[o] = 0.f; g_Yi[o] = 0.f; return; }
    int m = g_midx[j];
    float xr = 0.f, xi = 0.f;
    #pragma unroll
    for (int ns = 0; ns < NSPLIT; ns++) {
        size_t idx = ((size_t)(ns*BB + b)*CC + c)*MP + j;
        xr += g_Xr[idx];
        xi += g_Xi[idx];
    }
    xr *=  (1.f/(float)NN);
    xi *= -(1.f/(float)NN);
    float g = g_gate[b*MM+m];
    float wrv = wr[c*MM+m], wiv = wi[c*MM+m];
    g_Yr[o] = g*(xr*wrv - xi*wiv);
    g_Yi[o] = g*(xr*wiv + xi*wrv);
}

// ---------------- kernel 3: synthesis (software-pipelined basis + GEMM) ----------------
// block: 128 n x 64 c, j-tiles of 16; thread tile 4c x 8n
__global__ void __launch_bounds__(256) k_synth(const float* __restrict__ z,
                                               const float* __restrict__ bias,
                                               float* __restrict__ out)
{
    int nt = blockIdx.x, b = blockIdx.y;
    int n0 = nt*128;
    __shared__ float zs[128], zp[128];
    __shared__ float kk[MP], cc2[MP], ii[MP];
    __shared__ float yrb[2][16][68], yib[2][16][68];
    __shared__ float cwb[2][16][136], swb[2][16][136];

    int tid = threadIdx.x;
    if (tid < 128) {
        float zv = z[b*NN + n0 + tid];
        zs[tid] = zv;
        zp[tid] = zv*(1.f/PI_F);
    }
    for (int j = tid; j < MP; j += 256) {
        kk[j] = g_kcpt[j]; cc2[j] = g_ccpt[j]; ii[j] = g_iwcpt[j];
    }
    int ni = tid & 15, ci = tid >> 4;
    float acc[4][8];
    #pragma unroll
    for (int a = 0; a < 4; a++)
        #pragma unroll
        for (int d = 0; d < 8; d++) acc[a][d] = 0.f;

    int Mact = g_Mact;
    int T = (Mact + 15) >> 4;
    int cl = tid >> 2, ql = tid & 3;
    size_t ybase = ((size_t)b*CC + cl)*MP;
    __syncthreads();   // zs/kk visible

#define S_LOADY(t, bf) { \
    int j0_ = (t)*16; \
    float4 vr_ = *(const float4*)&g_Yr[ybase + j0_ + ql*4]; \
    float4 vi_ = *(const float4*)&g_Yi[ybase + j0_ + ql*4]; \
    yrb[bf][ql*4+0][cl]=vr_.x; yrb[bf][ql*4+1][cl]=vr_.y; yrb[bf][ql*4+2][cl]=vr_.z; yrb[bf][ql*4+3][cl]=vr_.w; \
    yib[bf][ql*4+0][cl]=vi_.x; yib[bf][ql*4+1][cl]=vi_.y; yib[bf][ql*4+2][cl]=vi_.z; yib[bf][ql*4+3][cl]=vi_.w; }

#define S_GENB(t, bf) { \
    int j0_ = (t)*16; \
    _Pragma("unroll") \
    for (int e_ = 0; e_ < 8; e_++) { \
        int idx_ = e_*256 + tid; \
        int jj_ = idx_ >> 7, nnb_ = idx_ & 127; \
        float s_, c_; __sincosf(zs[nnb_]*kk[j0_+jj_], &s_, &c_); \
        float d_ = (zp[nnb_] - cc2[j0_+jj_])*ii[j0_+jj_]; \
        float w_ = __expf(-0.5f*d_*d_); \
        cwb[bf][jj_][nnb_] = c_*w_; swb[bf][jj_][nnb_] = s_*w_; } }

    S_LOADY(0, 0);
    S_GENB(0, 0);
    __syncthreads();

    for (int t = 0; t < T; t++) {
        int cur = t & 1;
        if (t + 1 < T) {
            int nxt = cur ^ 1;
            S_LOADY(t+1, nxt);
            S_GENB(t+1, nxt);
        }
        #pragma unroll 2
        for (int jj = 0; jj < 16; jj++) {
            float4 yrv = *(const float4*)&yrb[cur][jj][ci*4];
            float4 yiv = *(const float4*)&yib[cur][jj][ci*4];
            float4 c0 = *(const float4*)&cwb[cur][jj][ni*8];
            float4 c1 = *(const float4*)&cwb[cur][jj][ni*8+4];
            float4 s0 = *(const float4*)&swb[cur][jj][ni*8];
            float4 s1 = *(const float4*)&swb[cur][jj][ni*8+4];
            float yra[4] = {yrv.x, yrv.y, yrv.z, yrv.w};
            float yia[4] = {yiv.x, yiv.y, yiv.z, yiv.w};
            float cwa[8] = {c0.x,c0.y,c0.z,c0.w,c1.x,c1.y,c1.z,c1.w};
            float swa[8] = {s0.x,s0.y,s0.z,s0.w,s1.x,s1.y,s1.z,s1.w};
            #pragma unroll
            for (int a = 0; a < 4; a++)
                #pragma unroll
                for (int d = 0; d < 8; d++)
                    acc[a][d] = fmaf(yra[a], cwa[d], fmaf(-yia[a], swa[d], acc[a][d]));
        }
        __syncthreads();
    }

    #pragma unroll
    for (int a = 0; a < 4; a++) {
        int c = ci*4 + a;
        float bv = bias[c];
        float4 o0, o1;
        o0.x = acc[a][0]+bv; o0.y = acc[a][1]+bv; o0.z = acc[a][2]+bv; o0.w = acc[a][3]+bv;
        o1.x = acc[a][4]+bv; o1.y = acc[a][5]+bv; o1.z = acc[a][6]+bv; o1.w = acc[a][7]+bv;
        float* op = out + ((size_t)(b*CC + c))*NN + n0 + ni*8;
        *(float4*)op = o0;
        *(float4*)(op+4) = o1;
    }
#undef S_LOADY
#undef S_GENB
}

// ---------------- launch ----------------
extern "C" void kernel_launch(void* const* d_in, const int* in_sizes, int n_in,
                              void* d_out, int out_size)
{
    const float* x_feat          = (const float*)d_in[0];
    const float* z               = (const float*)d_in[1];
    const float* temb            = (const float*)d_in[2];
    const float* kappa_raw       = (const float*)d_in[3];
    const float* gabor_c         = (const float*)d_in[4];
    const float* gabor_omega_raw = (const float*)d_in[5];
    const float* wr              = (const float*)d_in[6];
    const float* wi              = (const float*)d_in[7];
    const float* bias            = (const float*)d_in[8];
    const float* tproj_w         = (const float*)d_in[9];
    const float* tproj_b         = (const float*)d_in[10];
    const float* mlp_w1          = (const float*)d_in[11];
    const float* mlp_b1          = (const float*)d_in[12];
    const float* mlp_w2          = (const float*)d_in[13];
    const float* mlp_b2          = (const float*)d_in[14];
    const float* tau0            = (const float*)d_in[15];
    const float* tau1            = (const float*)d_in[16];
    const float* alphar          = (const float*)d_in[17];
    const float* glow            = (const float*)d_in[18];
    const float* gmid            = (const float*)d_in[19];
    const float* ghigh           = (const float*)d_in[20];
    float* out = (float*)d_out;

    k_batch<<<BB, 256>>>(temb, tproj_w, tproj_b, mlp_w1, mlp_b1, mlp_w2, mlp_b2, tau0, tau1);
    k_kappa<<<1, 256>>>(kappa_raw, gabor_c, gabor_omega_raw, alphar, glow, gmid, ghigh);
    dim3 g1((MM + 31)/32, NSPLIT, BB);     // (9, 16, 16); inactive m-tiles early-exit
    k_analysis<<<g1, 256>>>(x_feat, z);
    k_comb<<<BB*CC, MP>>>(wr, wi);
    dim3 g2(NN/128, BB);                   // (32, 16)
    k_synth<<<g2, 256>>>(z, bias, out);
}